// round 1
// baseline (speedup 1.0000x reference)
#include <cuda_runtime.h>
#include <cuda_bf16.h>

#define N_SPK 2048
#define M_UTT 8
#define D_EMB 512
#define N_ROWS (N_SPK * M_UTT)

#define TM 64
#define TN 64
#define TK 32

// Scratch (device globals: no allocation allowed in kernel_launch)
__device__ float g_centroid[N_SPK * D_EMB];
__device__ float g_diag[N_ROWS];

// ---------------------------------------------------------------------------
// Kernel A: per-speaker prep.
//   s = sum_m e_m ; centroid = s / |s|
//   diag(n,m) = (e_m . s - 1) / sqrt(|s|^2 - 2 e_m.s + 1)   (LOO cosine)
// Also zeroes the output accumulator (block 0).
// ---------------------------------------------------------------------------
__global__ __launch_bounds__(64) void prep_kernel(const float* __restrict__ e,
                                                  float* __restrict__ out) {
    int n = blockIdx.x;
    int t = threadIdx.x;  // 64 threads, 8 floats each
    const float* base = e + (size_t)n * (M_UTT * D_EMB) + t * 8;

    float4 r0[M_UTT], r1[M_UTT];
    float s[8];
#pragma unroll
    for (int j = 0; j < 8; ++j) s[j] = 0.f;
#pragma unroll
    for (int m = 0; m < M_UTT; ++m) {
        r0[m] = *(const float4*)(base + m * D_EMB);
        r1[m] = *(const float4*)(base + m * D_EMB + 4);
        s[0] += r0[m].x; s[1] += r0[m].y; s[2] += r0[m].z; s[3] += r0[m].w;
        s[4] += r1[m].x; s[5] += r1[m].y; s[6] += r1[m].z; s[7] += r1[m].w;
    }

    float p[9];
    p[8] = s[0]*s[0]+s[1]*s[1]+s[2]*s[2]+s[3]*s[3]
         + s[4]*s[4]+s[5]*s[5]+s[6]*s[6]+s[7]*s[7];
#pragma unroll
    for (int m = 0; m < M_UTT; ++m) {
        p[m] = r0[m].x*s[0]+r0[m].y*s[1]+r0[m].z*s[2]+r0[m].w*s[3]
             + r1[m].x*s[4]+r1[m].y*s[5]+r1[m].z*s[6]+r1[m].w*s[7];
    }

    __shared__ float red[2][9];
    int wid = t >> 5, lane = t & 31;
#pragma unroll
    for (int i = 0; i < 9; ++i) {
        float v = p[i];
#pragma unroll
        for (int off = 16; off > 0; off >>= 1)
            v += __shfl_xor_sync(0xffffffffu, v, off);
        if (lane == 0) red[wid][i] = v;
    }
    __syncthreads();

    float S2 = red[0][8] + red[1][8];
    float inv = rsqrtf(S2);
    float* c = g_centroid + (size_t)n * D_EMB + t * 8;
    *(float4*)c       = make_float4(s[0]*inv, s[1]*inv, s[2]*inv, s[3]*inv);
    *(float4*)(c + 4) = make_float4(s[4]*inv, s[5]*inv, s[6]*inv, s[7]*inv);

    if (t < M_UTT) {
        float tm = red[0][t] + red[1][t];
        g_diag[n * M_UTT + t] =
            (tm - 1.f) * rsqrtf(fmaxf(S2 - 2.f * tm + 1.f, 1e-20f));
    }
    if (n == 0 && t == 0) out[0] = 0.f;  // zero accumulator before loss kernel
}

// ---------------------------------------------------------------------------
// Kernel B: fused  sim = e @ centroid^T  +  diag replace  +  scale  +
//                  online logsumexp  +  loss accumulation.
// Block: 64 rows x (all 2048 cols in 64-wide tiles), 256 threads, 4x4 micro.
// ---------------------------------------------------------------------------
__global__ __launch_bounds__(256) void loss_kernel(const float* __restrict__ e,
                                                   const float* __restrict__ wp,
                                                   const float* __restrict__ bp,
                                                   float* __restrict__ out) {
    __shared__ float As[TK][TM];
    __shared__ float Bs[TK][TN];
    __shared__ float part[16];

    const int tid = threadIdx.x;
    const int tx = tid & 15;   // column group (4 cols)
    const int ty = tid >> 4;   // row group (4 rows)
    const int row0 = blockIdx.x * TM;

    const float w = fabsf(*wp);
    const float bb = *bp;
    const float NEG_INF = __int_as_float(0xff800000u);

    float mx[4], sm[4], lbl[4];
#pragma unroll
    for (int i = 0; i < 4; ++i) { mx[i] = NEG_INF; sm[i] = 0.f; lbl[i] = NEG_INF; }

    for (int col0 = 0; col0 < N_SPK; col0 += TN) {
        float acc[4][4];
#pragma unroll
        for (int i = 0; i < 4; ++i)
#pragma unroll
            for (int j = 0; j < 4; ++j) acc[i][j] = 0.f;

        for (int k0 = 0; k0 < D_EMB; k0 += TK) {
            // Cooperative tile load: 64 rows x 32 k each for A and B (transposed
            // into smem so the inner loop reads along rows/cols contiguously).
#pragma unroll
            for (int l = 0; l < 2; ++l) {
                int f = tid * 2 + l;       // 0..511 float4 slots
                int r = f >> 3;            // tile row (8 float4 per row)
                int kk = (f & 7) * 4;      // k offset
                float4 va = *(const float4*)(e + (size_t)(row0 + r) * D_EMB + k0 + kk);
                As[kk + 0][r] = va.x; As[kk + 1][r] = va.y;
                As[kk + 2][r] = va.z; As[kk + 3][r] = va.w;
                float4 vb = *(const float4*)(g_centroid + (size_t)(col0 + r) * D_EMB + k0 + kk);
                Bs[kk + 0][r] = vb.x; Bs[kk + 1][r] = vb.y;
                Bs[kk + 2][r] = vb.z; Bs[kk + 3][r] = vb.w;
            }
            __syncthreads();
#pragma unroll
            for (int k = 0; k < TK; ++k) {
                float4 av = *(const float4*)&As[k][ty * 4];
                float4 bv = *(const float4*)&Bs[k][tx * 4];
                float a[4] = {av.x, av.y, av.z, av.w};
                float bq[4] = {bv.x, bv.y, bv.z, bv.w};
#pragma unroll
                for (int i = 0; i < 4; ++i)
#pragma unroll
                    for (int j = 0; j < 4; ++j) acc[i][j] += a[i] * bq[j];
            }
            __syncthreads();
        }

        // Logit transform + diagonal replacement + online softmax update
#pragma unroll
        for (int i = 0; i < 4; ++i) {
            int rg = row0 + ty * 4 + i;
            int spk = rg >> 3;  // row / M_UTT
            float lg[4];
#pragma unroll
            for (int j = 0; j < 4; ++j) {
                int k = col0 + tx * 4 + j;
                float v = w * acc[i][j] + bb;
                if (k == spk) { v = w * g_diag[rg] + bb; lbl[i] = v; }
                lg[j] = v;
            }
            float tmx = fmaxf(fmaxf(lg[0], lg[1]), fmaxf(lg[2], lg[3]));
            float nm = fmaxf(mx[i], tmx);
            float ss = __expf(lg[0] - nm) + __expf(lg[1] - nm)
                     + __expf(lg[2] - nm) + __expf(lg[3] - nm);
            sm[i] = sm[i] * __expf(mx[i] - nm) + ss;
            mx[i] = nm;
        }
    }

    // Combine the 16 column-partials per row (16 contiguous lanes, width-16 xor)
    float bsum = 0.f;
#pragma unroll
    for (int i = 0; i < 4; ++i) {
        float m = mx[i], s = sm[i], L = lbl[i];
#pragma unroll
        for (int off = 8; off > 0; off >>= 1) {
            float om = __shfl_xor_sync(0xffffffffu, m, off, 16);
            float os = __shfl_xor_sync(0xffffffffu, s, off, 16);
            float oL = __shfl_xor_sync(0xffffffffu, L, off, 16);
            float nm = fmaxf(m, om);
            s = s * __expf(m - nm) + os * __expf(om - nm);
            m = nm;
            L = fmaxf(L, oL);
        }
        if (tx == 0) bsum += (m + __logf(s)) - L;  // lse - label_logit
    }
    if (tx == 0) part[ty] = bsum;
    __syncthreads();
    if (tid == 0) {
        float tsum = 0.f;
#pragma unroll
        for (int i = 0; i < 16; ++i) tsum += part[i];
        atomicAdd(out, tsum * (1.0f / N_ROWS));
    }
}

// ---------------------------------------------------------------------------
extern "C" void kernel_launch(void* const* d_in, const int* in_sizes, int n_in,
                              void* d_out, int out_size) {
    const float* e = (const float*)d_in[0];   // embeds [16384*512] f32
    const float* w = (const float*)d_in[1];   // scalar
    const float* b = (const float*)d_in[2];   // scalar
    float* out = (float*)d_out;               // scalar f32 loss

    prep_kernel<<<N_SPK, 64>>>(e, out);
    loss_kernel<<<N_ROWS / TM, 256>>>(e, w, b, out);
}

// round 4
// speedup vs baseline: 7.7212x; 7.7212x over previous
#include <cuda_runtime.h>
#include <cuda_bf16.h>
#include <cstdint>

#define N_SPK 2048
#define M_UTT 8
#define D_EMB 512
#define N_ROWS (N_SPK * M_UTT)

#define MT 128                    // rows per CTA
#define NT 128                    // cols per pass
#define NPASS (N_SPK / NT)        // 16
#define KCH 64                    // k per B chunk
#define NKC (D_EMB / KCH)         // 8
#define TOTCH (NPASS * NKC)       // 128 chunks total

// ---- dynamic shared memory layout ----
#define SM_A 0                        // 128 x 512 bf16, 8 chunks x 16384B
#define SM_B (MT * D_EMB * 2)         // 131072: 2 x (128 x 64 bf16 = 16384B)
#define SMEM_TOTAL (SM_B + 2 * NT * KCH * 2)   // 163840

// ---- device scratch (no allocation allowed) ----
__device__ float g_diag[N_ROWS];
__device__ __nv_bfloat16 g_ebf[(size_t)N_ROWS * D_EMB];
__device__ __nv_bfloat16 g_cbf[(size_t)N_SPK * D_EMB];

// ---------------------------------------------------------------- helpers
__device__ __forceinline__ uint32_t smem_u32(const void* p) {
    uint32_t a;
    asm("{ .reg .u64 t; cvta.to.shared.u64 t, %1; cvt.u32.u64 %0, t; }"
        : "=r"(a) : "l"(p));
    return a;
}
__device__ __forceinline__ uint32_t sw128(uint32_t off) {
    return off ^ ((off >> 3) & 0x70);
}
__device__ __forceinline__ void ldsm_x4(uint32_t* r, uint32_t a) {
    asm volatile("ldmatrix.sync.aligned.m8n8.x4.shared.b16 {%0,%1,%2,%3}, [%4];"
                 : "=r"(r[0]), "=r"(r[1]), "=r"(r[2]), "=r"(r[3]) : "r"(a));
}
__device__ __forceinline__ void ldsm_x4t(uint32_t* r, uint32_t a) {
    asm volatile("ldmatrix.sync.aligned.m8n8.x4.trans.shared.b16 {%0,%1,%2,%3}, [%4];"
                 : "=r"(r[0]), "=r"(r[1]), "=r"(r[2]), "=r"(r[3]) : "r"(a));
}
__device__ __forceinline__ void mma16816(float* c, const uint32_t* a,
                                         uint32_t b0, uint32_t b1) {
    asm volatile(
        "mma.sync.aligned.m16n8k16.row.col.f32.bf16.bf16.f32 "
        "{%0,%1,%2,%3}, {%4,%5,%6,%7}, {%8,%9}, {%0,%1,%2,%3};"
        : "+f"(c[0]), "+f"(c[1]), "+f"(c[2]), "+f"(c[3])
        : "r"(a[0]), "r"(a[1]), "r"(a[2]), "r"(a[3]), "r"(b0), "r"(b1));
}
#define CPASYNC16(dst, src)                                                   \
    asm volatile("cp.async.ca.shared.global [%0], [%1], 16;" ::"r"(dst),      \
                 "l"(src) : "memory")
#define CPCOMMIT() asm volatile("cp.async.commit_group;" ::: "memory")
#define CPWAIT1() asm volatile("cp.async.wait_group 1;" ::: "memory")
#define CPWAIT0() asm volatile("cp.async.wait_group 0;" ::: "memory")

// ---------------------------------------------------------------------------
// Kernel A: per-speaker prep: centroids, LOO diag values, bf16 conversions.
// ---------------------------------------------------------------------------
__global__ __launch_bounds__(64) void prep_kernel(const float* __restrict__ e,
                                                  float* __restrict__ out) {
    int n = blockIdx.x;
    int t = threadIdx.x;  // 64 threads x 8 floats
    const float* base = e + (size_t)n * (M_UTT * D_EMB) + t * 8;

    float4 r0[M_UTT], r1[M_UTT];
    float s[8];
#pragma unroll
    for (int j = 0; j < 8; ++j) s[j] = 0.f;
#pragma unroll
    for (int m = 0; m < M_UTT; ++m) {
        r0[m] = *(const float4*)(base + m * D_EMB);
        r1[m] = *(const float4*)(base + m * D_EMB + 4);
        s[0] += r0[m].x; s[1] += r0[m].y; s[2] += r0[m].z; s[3] += r0[m].w;
        s[4] += r1[m].x; s[5] += r1[m].y; s[6] += r1[m].z; s[7] += r1[m].w;
    }

    // bf16 copy of the 8 utterance rows
#pragma unroll
    for (int m = 0; m < M_UTT; ++m) {
        __nv_bfloat162 p0 = __floats2bfloat162_rn(r0[m].x, r0[m].y);
        __nv_bfloat162 p1 = __floats2bfloat162_rn(r0[m].z, r0[m].w);
        __nv_bfloat162 p2 = __floats2bfloat162_rn(r1[m].x, r1[m].y);
        __nv_bfloat162 p3 = __floats2bfloat162_rn(r1[m].z, r1[m].w);
        uint4 v = make_uint4(*(uint32_t*)&p0, *(uint32_t*)&p1,
                             *(uint32_t*)&p2, *(uint32_t*)&p3);
        *(uint4*)&g_ebf[((size_t)n * M_UTT + m) * D_EMB + t * 8] = v;
    }

    float p[9];
    p[8] = s[0]*s[0]+s[1]*s[1]+s[2]*s[2]+s[3]*s[3]
         + s[4]*s[4]+s[5]*s[5]+s[6]*s[6]+s[7]*s[7];
#pragma unroll
    for (int m = 0; m < M_UTT; ++m) {
        p[m] = r0[m].x*s[0]+r0[m].y*s[1]+r0[m].z*s[2]+r0[m].w*s[3]
             + r1[m].x*s[4]+r1[m].y*s[5]+r1[m].z*s[6]+r1[m].w*s[7];
    }

    __shared__ float red[2][9];
    int wid = t >> 5, lane = t & 31;
#pragma unroll
    for (int i = 0; i < 9; ++i) {
        float v = p[i];
#pragma unroll
        for (int off = 16; off > 0; off >>= 1)
            v += __shfl_xor_sync(0xffffffffu, v, off);
        if (lane == 0) red[wid][i] = v;
    }
    __syncthreads();

    float S2 = red[0][8] + red[1][8];
    float inv = rsqrtf(S2);
    {
        __nv_bfloat162 p0 = __floats2bfloat162_rn(s[0]*inv, s[1]*inv);
        __nv_bfloat162 p1 = __floats2bfloat162_rn(s[2]*inv, s[3]*inv);
        __nv_bfloat162 p2 = __floats2bfloat162_rn(s[4]*inv, s[5]*inv);
        __nv_bfloat162 p3 = __floats2bfloat162_rn(s[6]*inv, s[7]*inv);
        uint4 v = make_uint4(*(uint32_t*)&p0, *(uint32_t*)&p1,
                             *(uint32_t*)&p2, *(uint32_t*)&p3);
        *(uint4*)&g_cbf[(size_t)n * D_EMB + t * 8] = v;
    }

    if (t < M_UTT) {
        float tm = red[0][t] + red[1][t];
        g_diag[n * M_UTT + t] =
            (tm - 1.f) * rsqrtf(fmaxf(S2 - 2.f * tm + 1.f, 1e-20f));
    }
    if (n == 0 && t == 0) out[0] = 0.f;
}

// ---------------------------------------------------------------------------
// Kernel B: mma.sync bf16 GEMM (128 x 2048 x 512 per CTA) fused with
// softmax-sum + cross-entropy. Logits are bounded by |w|+|b| so no max
// tracking is needed: loss_row = log(sum exp(x)) - x_label.
// ---------------------------------------------------------------------------
__global__ __launch_bounds__(256, 1)
void loss_kernel(const float* __restrict__ wp, const float* __restrict__ bp,
                 float* __restrict__ out) {
    extern __shared__ char smem[];
    const uint32_t sb = smem_u32(smem);
    const int tid = threadIdx.x;
    const int wid = tid >> 5, l = tid & 31;
    const int row0 = blockIdx.x * MT;

    // ---- A tile: 128 rows x 512 bf16, 8 k-chunks of 128B, SW128 swizzled
    {
        const char* src = (const char*)g_ebf + (size_t)row0 * 1024;
        for (int i = tid; i < 8192; i += 256) {
            int r = i >> 6;            // row (64 x 16B per row)
            int bc = (i & 63) << 4;    // byte col in row
            uint4 v = *(const uint4*)(src + (size_t)r * 1024 + bc);
            int c = bc >> 7, b = bc & 127;
            *(uint4*)(smem + SM_A + c * 16384 + sw128(r * 128 + b)) = v;
        }
    }

    const float wa = fabsf(*wp), bb = *bp;
    const int grow0 = row0 + wid * 16 + (l >> 2);
    const int grow1 = grow0 + 8;
    const int spk0 = grow0 >> 3, spk1 = grow1 >> 3;
    const float dv0 = fmaf(wa, g_diag[grow0], bb);
    const float dv1 = fmaf(wa, g_diag[grow1], bb);

    // lane-invariant ldmatrix address components
    const uint32_t rA128 = (uint32_t)(wid * 16 + (l & 15)) * 128 + ((l >> 4) << 4);
    const uint32_t nB128 = (uint32_t)(((l >> 4) << 3) + (l & 7)) * 128 +
                           (((l >> 3) & 1) << 4);

    // B chunk cp.async issue: chunk g covers cols [pass*128,+128), k [kc*64,+64)
    auto issueB = [&](int g) {
        int pass = g >> 3, kc = g & 7;
        const char* src = (const char*)g_cbf + (size_t)(pass * NT) * 1024 + kc * 128;
        uint32_t dst = sb + SM_B + (g & 1) * 16384;
        for (int i = tid; i < 1024; i += 256) {
            int r = i >> 3, b = (i & 7) << 4;
            CPASYNC16(dst + sw128(r * 128 + b),
                      (const void*)(src + (size_t)r * 1024 + b));
        }
        CPCOMMIT();
    };
    issueB(0);

    float s0 = 0.f, s1 = 0.f;
    for (int pass = 0; pass < NPASS; ++pass) {
        float acc[16][4];
#pragma unroll
        for (int f = 0; f < 16; ++f)
            acc[f][0] = acc[f][1] = acc[f][2] = acc[f][3] = 0.f;

        for (int kc = 0; kc < NKC; ++kc) {
            const int g = pass * NKC + kc;
            if (g + 1 < TOTCH) { issueB(g + 1); CPWAIT1(); } else { CPWAIT0(); }
            __syncthreads();
            const uint32_t abase = sb + SM_A + kc * 16384;
            const uint32_t bbase = sb + SM_B + (g & 1) * 16384;
#pragma unroll
            for (int ks = 0; ks < 4; ++ks) {
                uint32_t a[4];
                ldsm_x4(a, abase + sw128(rA128 + ks * 32));
#pragma unroll
                for (int f2 = 0; f2 < 8; ++f2) {
                    uint32_t b[4];
                    ldsm_x4t(b, bbase + sw128(nB128 + f2 * 2048 + ks * 32));
                    mma16816(acc[2 * f2],     a, b[0], b[1]);
                    mma16816(acc[2 * f2 + 1], a, b[2], b[3]);
                }
            }
            __syncthreads();
        }

        // ---- epilogue: scale + diag replace + exp-sum (overlaps next prefetch)
        const int n0 = pass * NT;
#pragma unroll
        for (int f = 0; f < 16; ++f) {
            const int c = n0 + f * 8 + (l & 3) * 2;
            float x00 = fmaf(wa, acc[f][0], bb); if (c     == spk0) x00 = dv0;
            float x01 = fmaf(wa, acc[f][1], bb); if (c + 1 == spk0) x01 = dv0;
            float x10 = fmaf(wa, acc[f][2], bb); if (c     == spk1) x10 = dv1;
            float x11 = fmaf(wa, acc[f][3], bb); if (c + 1 == spk1) x11 = dv1;
            s0 += __expf(x00) + __expf(x01);
            s1 += __expf(x10) + __expf(x11);
        }
    }

    // ---- per-row loss: reduce the 4 lanes sharing each row
    s0 += __shfl_xor_sync(0xffffffffu, s0, 1);
    s0 += __shfl_xor_sync(0xffffffffu, s0, 2);
    s1 += __shfl_xor_sync(0xffffffffu, s1, 1);
    s1 += __shfl_xor_sync(0xffffffffu, s1, 2);
    float part = 0.f;
    if ((l & 3) == 0)
        part = (__logf(s0) - dv0) + (__logf(s1) - dv1);
    part += __shfl_xor_sync(0xffffffffu, part, 4);
    part += __shfl_xor_sync(0xffffffffu, part, 8);
    part += __shfl_xor_sync(0xffffffffu, part, 16);
    if (l == 0) atomicAdd(out, part * (1.0f / N_ROWS));
}

// ---------------------------------------------------------------------------
extern "C" void kernel_launch(void* const* d_in, const int* in_sizes, int n_in,
                              void* d_out, int out_size) {
    const float* e = (const float*)d_in[0];   // embeds [16384,512] f32
    const float* w = (const float*)d_in[1];   // scalar
    const float* b = (const float*)d_in[2];   // scalar
    float* out = (float*)d_out;

    cudaFuncSetAttribute(loss_kernel, cudaFuncAttributeMaxDynamicSharedMemorySize,
                         SMEM_TOTAL);
    prep_kernel<<<N_SPK, 64>>>(e, out);
    loss_kernel<<<N_ROWS / MT, 256, SMEM_TOTAL>>>(w, b, out);
}

// round 6
// speedup vs baseline: 8.8160x; 1.1418x over previous
#include <cuda_runtime.h>
#include <cuda_bf16.h>
#include <cstdint>

#define N_SPK 2048
#define M_UTT 8
#define D_EMB 512
#define N_ROWS (N_SPK * M_UTT)

#define MT 128                    // rows per CTA
#define NT 128                    // cols per pass
#define NPASS (N_SPK / NT)        // 16
#define KCH 64                    // k per B chunk
#define NKC (D_EMB / KCH)         // 8
#define TOTCH (NPASS * NKC)       // 128 chunks total
#define NBUF 4                    // cp.async pipeline depth

// ---- dynamic shared memory layout ----
#define SM_A 0                            // 128 x 512 bf16 = 131072 B (8 chunks)
#define SM_B (MT * D_EMB * 2)             // 4 x (128 x 64 bf16 = 16384 B)
#define SM_RED (SM_B + NBUF * NT * KCH * 2)   // 128 floats row-sum exchange
#define SMEM_TOTAL (SM_RED + 512)

// ---- device scratch (no allocation allowed) ----
__device__ float g_diag[N_ROWS];
__device__ __nv_bfloat16 g_ebf[(size_t)N_ROWS * D_EMB];
__device__ __nv_bfloat16 g_cbf[(size_t)N_SPK * D_EMB];

// ---------------------------------------------------------------- helpers
__device__ __forceinline__ uint32_t smem_u32(const void* p) {
    uint32_t a;
    asm("{ .reg .u64 t; cvta.to.shared.u64 t, %1; cvt.u32.u64 %0, t; }"
        : "=r"(a) : "l"(p));
    return a;
}
__device__ __forceinline__ uint32_t sw128(uint32_t off) {
    return off ^ ((off >> 3) & 0x70);
}
__device__ __forceinline__ void ldsm_x4(uint32_t* r, uint32_t a) {
    asm volatile("ldmatrix.sync.aligned.m8n8.x4.shared.b16 {%0,%1,%2,%3}, [%4];"
                 : "=r"(r[0]), "=r"(r[1]), "=r"(r[2]), "=r"(r[3]) : "r"(a));
}
__device__ __forceinline__ void ldsm_x4t(uint32_t* r, uint32_t a) {
    asm volatile("ldmatrix.sync.aligned.m8n8.x4.trans.shared.b16 {%0,%1,%2,%3}, [%4];"
                 : "=r"(r[0]), "=r"(r[1]), "=r"(r[2]), "=r"(r[3]) : "r"(a));
}
__device__ __forceinline__ void mma16816(float* c, const uint32_t* a,
                                         uint32_t b0, uint32_t b1) {
    asm volatile(
        "mma.sync.aligned.m16n8k16.row.col.f32.bf16.bf16.f32 "
        "{%0,%1,%2,%3}, {%4,%5,%6,%7}, {%8,%9}, {%0,%1,%2,%3};"
        : "+f"(c[0]), "+f"(c[1]), "+f"(c[2]), "+f"(c[3])
        : "r"(a[0]), "r"(a[1]), "r"(a[2]), "r"(a[3]), "r"(b0), "r"(b1));
}
#define CPASYNC16(dst, src)                                                   \
    asm volatile("cp.async.ca.shared.global [%0], [%1], 16;" ::"r"(dst),      \
                 "l"(src) : "memory")
#define CPCOMMIT() asm volatile("cp.async.commit_group;" ::: "memory")
#define CPWAIT2() asm volatile("cp.async.wait_group 2;" ::: "memory")

// ---------------------------------------------------------------------------
// Kernel A: per-speaker prep: centroids, LOO diag values, bf16 conversions.
// ---------------------------------------------------------------------------
__global__ __launch_bounds__(64) void prep_kernel(const float* __restrict__ e,
                                                  float* __restrict__ out) {
    int n = blockIdx.x;
    int t = threadIdx.x;  // 64 threads x 8 floats
    const float* base = e + (size_t)n * (M_UTT * D_EMB) + t * 8;

    float4 r0[M_UTT], r1[M_UTT];
    float s[8];
#pragma unroll
    for (int j = 0; j < 8; ++j) s[j] = 0.f;
#pragma unroll
    for (int m = 0; m < M_UTT; ++m) {
        r0[m] = *(const float4*)(base + m * D_EMB);
        r1[m] = *(const float4*)(base + m * D_EMB + 4);
        s[0] += r0[m].x; s[1] += r0[m].y; s[2] += r0[m].z; s[3] += r0[m].w;
        s[4] += r1[m].x; s[5] += r1[m].y; s[6] += r1[m].z; s[7] += r1[m].w;
    }

#pragma unroll
    for (int m = 0; m < M_UTT; ++m) {
        __nv_bfloat162 p0 = __floats2bfloat162_rn(r0[m].x, r0[m].y);
        __nv_bfloat162 p1 = __floats2bfloat162_rn(r0[m].z, r0[m].w);
        __nv_bfloat162 p2 = __floats2bfloat162_rn(r1[m].x, r1[m].y);
        __nv_bfloat162 p3 = __floats2bfloat162_rn(r1[m].z, r1[m].w);
        uint4 v = make_uint4(*(uint32_t*)&p0, *(uint32_t*)&p1,
                             *(uint32_t*)&p2, *(uint32_t*)&p3);
        *(uint4*)&g_ebf[((size_t)n * M_UTT + m) * D_EMB + t * 8] = v;
    }

    float p[9];
    p[8] = s[0]*s[0]+s[1]*s[1]+s[2]*s[2]+s[3]*s[3]
         + s[4]*s[4]+s[5]*s[5]+s[6]*s[6]+s[7]*s[7];
#pragma unroll
    for (int m = 0; m < M_UTT; ++m) {
        p[m] = r0[m].x*s[0]+r0[m].y*s[1]+r0[m].z*s[2]+r0[m].w*s[3]
             + r1[m].x*s[4]+r1[m].y*s[5]+r1[m].z*s[6]+r1[m].w*s[7];
    }

    __shared__ float red[2][9];
    int wid = t >> 5, lane = t & 31;
#pragma unroll
    for (int i = 0; i < 9; ++i) {
        float v = p[i];
#pragma unroll
        for (int off = 16; off > 0; off >>= 1)
            v += __shfl_xor_sync(0xffffffffu, v, off);
        if (lane == 0) red[wid][i] = v;
    }
    __syncthreads();

    float S2 = red[0][8] + red[1][8];
    float inv = rsqrtf(S2);
    {
        __nv_bfloat162 p0 = __floats2bfloat162_rn(s[0]*inv, s[1]*inv);
        __nv_bfloat162 p1 = __floats2bfloat162_rn(s[2]*inv, s[3]*inv);
        __nv_bfloat162 p2 = __floats2bfloat162_rn(s[4]*inv, s[5]*inv);
        __nv_bfloat162 p3 = __floats2bfloat162_rn(s[6]*inv, s[7]*inv);
        uint4 v = make_uint4(*(uint32_t*)&p0, *(uint32_t*)&p1,
                             *(uint32_t*)&p2, *(uint32_t*)&p3);
        *(uint4*)&g_cbf[(size_t)n * D_EMB + t * 8] = v;
    }

    if (t < M_UTT) {
        float tm = red[0][t] + red[1][t];
        g_diag[n * M_UTT + t] =
            (tm - 1.f) * rsqrtf(fmaxf(S2 - 2.f * tm + 1.f, 1e-20f));
    }
    if (n == 0 && t == 0) out[0] = 0.f;
}

// ---------------------------------------------------------------------------
// Kernel B: mma.sync bf16 GEMM (128 x 2048 x 512 per CTA) fused with
// softmax-sum + cross-entropy. Warp tile 32x64 (4M x 2N warp grid),
// 4-deep cp.async B pipeline, one barrier per k-chunk.
// Per-row sums are combined across the two wn warps via smem before log().
// ---------------------------------------------------------------------------
__global__ __launch_bounds__(256, 1)
void loss_kernel(const float* __restrict__ wp, const float* __restrict__ bp,
                 float* __restrict__ out) {
    extern __shared__ char smem[];
    const uint32_t sb = smem_u32(smem);
    const int tid = threadIdx.x;
    const int wid = tid >> 5, l = tid & 31;
    const int wm = wid >> 1, wn = wid & 1;   // 4 x 2 warp grid
    const int row0 = blockIdx.x * MT;

    // ---- A tile: 128 rows x 512 bf16, 8 k-chunks of 128B, SW128 swizzled
    {
        const char* src = (const char*)g_ebf + (size_t)row0 * 1024;
        for (int i = tid; i < 8192; i += 256) {
            int r = i >> 6;
            int bc = (i & 63) << 4;
            uint4 v = *(const uint4*)(src + (size_t)r * 1024 + bc);
            int c = bc >> 7, b = bc & 127;
            *(uint4*)(smem + SM_A + c * 16384 + sw128(r * 128 + b)) = v;
        }
    }

    const float wa = fabsf(*wp), bb = *bp;

    // 4 rows owned by this thread within the CTA tile
    int rloc[4], spk[4];
    float dval[4];
#pragma unroll
    for (int q = 0; q < 4; ++q) {
        rloc[q] = wm * 32 + (q >> 1) * 16 + (q & 1) * 8 + (l >> 2);
        spk[q] = (row0 + rloc[q]) >> 3;
        dval[q] = fmaf(wa, g_diag[row0 + rloc[q]], bb);
    }

    // lane-invariant ldmatrix address components
    const uint32_t rA = (uint32_t)(wm * 32 + (l & 15)) * 128 + ((l >> 4) << 4);
    const uint32_t nB = (uint32_t)(((l >> 4) << 3) + (l & 7)) * 128 +
                        (((l >> 3) & 1) << 4) + (uint32_t)wn * 8192;

    // B chunk cp.async: chunk g covers cols [ (g>>3)*128, +128 ), k [ (g&7)*64, +64 )
    auto issueB = [&](int g) {
        if (g < TOTCH) {
            const char* src = (const char*)g_cbf + (size_t)(g >> 3) * (NT * 1024) +
                              (g & 7) * 128;
            uint32_t dst = sb + SM_B + (g & (NBUF - 1)) * 16384;
            for (int i = tid; i < 1024; i += 256) {
                int r = i >> 3, b = (i & 7) << 4;
                CPASYNC16(dst + sw128(r * 128 + b),
                          (const void*)(src + (size_t)r * 1024 + b));
            }
        }
        CPCOMMIT();   // empty group at tail keeps wait_group accounting aligned
    };
    issueB(0); issueB(1); issueB(2);

    float s[4] = {0.f, 0.f, 0.f, 0.f};
    for (int pass = 0; pass < NPASS; ++pass) {
        float acc[2][8][4];
#pragma unroll
        for (int rb = 0; rb < 2; ++rb)
#pragma unroll
            for (int f = 0; f < 8; ++f)
                acc[rb][f][0] = acc[rb][f][1] = acc[rb][f][2] = acc[rb][f][3] = 0.f;

        for (int kc = 0; kc < NKC; ++kc) {
            const int g = pass * NKC + kc;
            CPWAIT2();                 // chunk g resident (3 in flight max)
            __syncthreads();           // all warps done with chunk g-1's buffer
            issueB(g + 3);             // refill the buffer g-1 vacated

            const uint32_t abase = sb + SM_A + kc * 16384;
            const uint32_t bbase = sb + SM_B + (g & (NBUF - 1)) * 16384;
#pragma unroll
            for (int ks = 0; ks < 4; ++ks) {
                uint32_t a0[4], a1[4];
                ldsm_x4(a0, abase + sw128(rA + ks * 32));
                ldsm_x4(a1, abase + sw128(rA + 2048 + ks * 32));  // +16 rows
#pragma unroll
                for (int f2 = 0; f2 < 4; ++f2) {
                    uint32_t b[4];
                    ldsm_x4t(b, bbase + sw128(nB + f2 * 2048 + ks * 32));
                    mma16816(acc[0][2 * f2],     a0, b[0], b[1]);
                    mma16816(acc[0][2 * f2 + 1], a0, b[2], b[3]);
                    mma16816(acc[1][2 * f2],     a1, b[0], b[1]);
                    mma16816(acc[1][2 * f2 + 1], a1, b[2], b[3]);
                }
            }
        }

        // ---- epilogue: scale + diag replace + exp-sum over this warp's 64 cols
        const int n0 = pass * NT + wn * 64;
#pragma unroll
        for (int rb = 0; rb < 2; ++rb) {
#pragma unroll
            for (int f = 0; f < 8; ++f) {
                const int c = n0 + f * 8 + (l & 3) * 2;
                float x00 = fmaf(wa, acc[rb][f][0], bb);
                float x01 = fmaf(wa, acc[rb][f][1], bb);
                float x10 = fmaf(wa, acc[rb][f][2], bb);
                float x11 = fmaf(wa, acc[rb][f][3], bb);
                if (c     == spk[rb * 2])     x00 = dval[rb * 2];
                if (c + 1 == spk[rb * 2])     x01 = dval[rb * 2];
                if (c     == spk[rb * 2 + 1]) x10 = dval[rb * 2 + 1];
                if (c + 1 == spk[rb * 2 + 1]) x11 = dval[rb * 2 + 1];
                s[rb * 2]     += __expf(x00) + __expf(x01);
                s[rb * 2 + 1] += __expf(x10) + __expf(x11);
            }
        }
    }

    // ---- reduce the 4 lanes (quad) sharing each row (within this warp's half)
#pragma unroll
    for (int q = 0; q < 4; ++q) {
        s[q] += __shfl_xor_sync(0xffffffffu, s[q], 1);
        s[q] += __shfl_xor_sync(0xffffffffu, s[q], 2);
    }

    // ---- combine the two column-half warps (wn=0/1) per row via smem
    float* red = (float*)(smem + SM_RED);
    __syncthreads();
    if (wn == 1 && (l & 3) == 0) {
#pragma unroll
        for (int q = 0; q < 4; ++q) red[rloc[q]] = s[q];
    }
    __syncthreads();
    float part = 0.f;
    if (wn == 0 && (l & 3) == 0) {
#pragma unroll
        for (int q = 0; q < 4; ++q)
            part += __logf(s[q] + red[rloc[q]]) - dval[q];
    }
    part += __shfl_xor_sync(0xffffffffu, part, 4);
    part += __shfl_xor_sync(0xffffffffu, part, 8);
    part += __shfl_xor_sync(0xffffffffu, part, 16);
    if (wn == 0 && l == 0) atomicAdd(out, part * (1.0f / N_ROWS));
}

// ---------------------------------------------------------------------------
extern "C" void kernel_launch(void* const* d_in, const int* in_sizes, int n_in,
                              void* d_out, int out_size) {
    const float* e = (const float*)d_in[0];   // embeds [16384,512] f32
    const float* w = (const float*)d_in[1];   // scalar
    const float* b = (const float*)d_in[2];   // scalar
    float* out = (float*)d_out;

    cudaFuncSetAttribute(loss_kernel, cudaFuncAttributeMaxDynamicSharedMemorySize,
                         SMEM_TOTAL);
    prep_kernel<<<N_SPK, 64>>>(e, out);
    loss_kernel<<<N_ROWS / MT, 256, SMEM_TOTAL>>>(w, b, out);
}

// round 7
// speedup vs baseline: 10.0411x; 1.1390x over previous
#include <cuda_runtime.h>
#include <cuda_bf16.h>
#include <cstdint>

#define N_SPK 2048
#define M_UTT 8
#define D_EMB 512
#define N_ROWS (N_SPK * M_UTT)

#define MT 128                    // rows per CTA
#define NT 256                    // cols per pass
#define NPASS (N_SPK / NT)        // 8
#define KCH 64                    // k per B chunk
#define NKC (D_EMB / KCH)         // 8
#define TOTCH (NPASS * NKC)       // 64 chunks total
#define NBUF 2                    // B double buffer (32KB each)

// ---- dynamic shared memory layout ----
#define SM_A 0                              // 128 x 512 bf16 = 131072 B (8 chunks)
#define SM_B (MT * D_EMB * 2)               // 2 x (256 x 64 bf16 = 32768 B)
#define SM_RED (SM_B + NBUF * NT * KCH * 2) // 3 x 128 floats
#define SMEM_TOTAL (SM_RED + 1536 + 64)

// ---- device scratch (no allocation allowed) ----
__device__ float g_diag[N_ROWS];
__device__ __nv_bfloat16 g_ebf[(size_t)N_ROWS * D_EMB];
__device__ __nv_bfloat16 g_cbf[(size_t)N_SPK * D_EMB];

// ---------------------------------------------------------------- helpers
__device__ __forceinline__ uint32_t smem_u32(const void* p) {
    uint32_t a;
    asm("{ .reg .u64 t; cvta.to.shared.u64 t, %1; cvt.u32.u64 %0, t; }"
        : "=r"(a) : "l"(p));
    return a;
}
__device__ __forceinline__ uint32_t sw128(uint32_t off) {
    return off ^ ((off >> 3) & 0x70);
}
__device__ __forceinline__ void ldsm_x4(uint32_t* r, uint32_t a) {
    asm volatile("ldmatrix.sync.aligned.m8n8.x4.shared.b16 {%0,%1,%2,%3}, [%4];"
                 : "=r"(r[0]), "=r"(r[1]), "=r"(r[2]), "=r"(r[3]) : "r"(a));
}
__device__ __forceinline__ void ldsm_x4t(uint32_t* r, uint32_t a) {
    asm volatile("ldmatrix.sync.aligned.m8n8.x4.trans.shared.b16 {%0,%1,%2,%3}, [%4];"
                 : "=r"(r[0]), "=r"(r[1]), "=r"(r[2]), "=r"(r[3]) : "r"(a));
}
__device__ __forceinline__ void mma16816(float* c, const uint32_t* a,
                                         uint32_t b0, uint32_t b1) {
    asm volatile(
        "mma.sync.aligned.m16n8k16.row.col.f32.bf16.bf16.f32 "
        "{%0,%1,%2,%3}, {%4,%5,%6,%7}, {%8,%9}, {%0,%1,%2,%3};"
        : "+f"(c[0]), "+f"(c[1]), "+f"(c[2]), "+f"(c[3])
        : "r"(a[0]), "r"(a[1]), "r"(a[2]), "r"(a[3]), "r"(b0), "r"(b1));
}
#define CPASYNC16(dst, src)                                                   \
    asm volatile("cp.async.ca.shared.global [%0], [%1], 16;" ::"r"(dst),      \
                 "l"(src) : "memory")
#define CPCOMMIT() asm volatile("cp.async.commit_group;" ::: "memory")
#define CPWAIT0() asm volatile("cp.async.wait_group 0;" ::: "memory")

// ---------------------------------------------------------------------------
// Kernel A: per-speaker prep: centroids, LOO diag values, bf16 conversions.
// ---------------------------------------------------------------------------
__global__ __launch_bounds__(64) void prep_kernel(const float* __restrict__ e,
                                                  float* __restrict__ out) {
    int n = blockIdx.x;
    int t = threadIdx.x;  // 64 threads x 8 floats
    const float* base = e + (size_t)n * (M_UTT * D_EMB) + t * 8;

    float4 r0[M_UTT], r1[M_UTT];
    float s[8];
#pragma unroll
    for (int j = 0; j < 8; ++j) s[j] = 0.f;
#pragma unroll
    for (int m = 0; m < M_UTT; ++m) {
        r0[m] = *(const float4*)(base + m * D_EMB);
        r1[m] = *(const float4*)(base + m * D_EMB + 4);
        s[0] += r0[m].x; s[1] += r0[m].y; s[2] += r0[m].z; s[3] += r0[m].w;
        s[4] += r1[m].x; s[5] += r1[m].y; s[6] += r1[m].z; s[7] += r1[m].w;
    }

#pragma unroll
    for (int m = 0; m < M_UTT; ++m) {
        __nv_bfloat162 p0 = __floats2bfloat162_rn(r0[m].x, r0[m].y);
        __nv_bfloat162 p1 = __floats2bfloat162_rn(r0[m].z, r0[m].w);
        __nv_bfloat162 p2 = __floats2bfloat162_rn(r1[m].x, r1[m].y);
        __nv_bfloat162 p3 = __floats2bfloat162_rn(r1[m].z, r1[m].w);
        uint4 v = make_uint4(*(uint32_t*)&p0, *(uint32_t*)&p1,
                             *(uint32_t*)&p2, *(uint32_t*)&p3);
        *(uint4*)&g_ebf[((size_t)n * M_UTT + m) * D_EMB + t * 8] = v;
    }

    float p[9];
    p[8] = s[0]*s[0]+s[1]*s[1]+s[2]*s[2]+s[3]*s[3]
         + s[4]*s[4]+s[5]*s[5]+s[6]*s[6]+s[7]*s[7];
#pragma unroll
    for (int m = 0; m < M_UTT; ++m) {
        p[m] = r0[m].x*s[0]+r0[m].y*s[1]+r0[m].z*s[2]+r0[m].w*s[3]
             + r1[m].x*s[4]+r1[m].y*s[5]+r1[m].z*s[6]+r1[m].w*s[7];
    }

    __shared__ float red[2][9];
    int wid = t >> 5, lane = t & 31;
#pragma unroll
    for (int i = 0; i < 9; ++i) {
        float v = p[i];
#pragma unroll
        for (int off = 16; off > 0; off >>= 1)
            v += __shfl_xor_sync(0xffffffffu, v, off);
        if (lane == 0) red[wid][i] = v;
    }
    __syncthreads();

    float S2 = red[0][8] + red[1][8];
    float inv = rsqrtf(S2);
    {
        __nv_bfloat162 p0 = __floats2bfloat162_rn(s[0]*inv, s[1]*inv);
        __nv_bfloat162 p1 = __floats2bfloat162_rn(s[2]*inv, s[3]*inv);
        __nv_bfloat162 p2 = __floats2bfloat162_rn(s[4]*inv, s[5]*inv);
        __nv_bfloat162 p3 = __floats2bfloat162_rn(s[6]*inv, s[7]*inv);
        uint4 v = make_uint4(*(uint32_t*)&p0, *(uint32_t*)&p1,
                             *(uint32_t*)&p2, *(uint32_t*)&p3);
        *(uint4*)&g_cbf[(size_t)n * D_EMB + t * 8] = v;
    }

    if (t < M_UTT) {
        float tm = red[0][t] + red[1][t];
        g_diag[n * M_UTT + t] =
            (tm - 1.f) * rsqrtf(fmaxf(S2 - 2.f * tm + 1.f, 1e-20f));
    }
    if (n == 0 && t == 0) out[0] = 0.f;
}

// ---------------------------------------------------------------------------
// Kernel B: mma.sync bf16 GEMM (128 x 2048 x 512 per CTA) fused with
// softmax-sum + cross-entropy. Warp tile 64x64 (2M x 4N warp grid, 8 warps),
// NT=256-col passes, double-buffered 32KB B chunks (copy g+1 overlaps
// compute g and the epilogue). Logits bounded: plain exp-sum, no max.
// ---------------------------------------------------------------------------
__global__ __launch_bounds__(256, 1)
void loss_kernel(const float* __restrict__ wp, const float* __restrict__ bp,
                 float* __restrict__ out) {
    extern __shared__ char smem[];
    const uint32_t sb = smem_u32(smem);
    const int tid = threadIdx.x;
    const int wid = tid >> 5, l = tid & 31;
    const int wm = wid >> 2, wn = wid & 3;   // 2 x 4 warp grid
    const int row0 = blockIdx.x * MT;

    // B chunk cp.async: chunk g covers cols [(g>>3)*256,+256), k [(g&7)*64,+64)
    auto issueB = [&](int g) {
        if (g < TOTCH) {
            const char* src = (const char*)g_cbf + (size_t)(g >> 3) * (NT * 1024) +
                              (g & 7) * 128;
            uint32_t dst = sb + SM_B + (g & 1) * 32768;
            for (int i = tid; i < 2048; i += 256) {
                int r = i >> 3, b = (i & 7) << 4;
                CPASYNC16(dst + sw128(r * 128 + b),
                          (const void*)(src + (size_t)r * 1024 + b));
            }
            CPCOMMIT();
        }
    };
    issueB(0);

    // ---- A tile: 128 rows x 512 bf16, 8 k-chunks of 128B, SW128 swizzled
    {
        const char* src = (const char*)g_ebf + (size_t)row0 * 1024;
        for (int i = tid; i < 8192; i += 256) {
            int r = i >> 6;
            int bc = (i & 63) << 4;
            uint4 v = *(const uint4*)(src + (size_t)r * 1024 + bc);
            int c = bc >> 7, b = bc & 127;
            *(uint4*)(smem + SM_A + c * 16384 + sw128(r * 128 + b)) = v;
        }
    }

    const float wa = fabsf(*wp), bb = *bp;

    // 8 rows owned by this thread: q = rb*2+h -> wm*64 + rb*16 + h*8 + (l>>2)
    int rloc[8], spk[8];
    float dval[8];
#pragma unroll
    for (int q = 0; q < 8; ++q) {
        rloc[q] = wm * 64 + (q >> 1) * 16 + (q & 1) * 8 + (l >> 2);
        spk[q] = (row0 + rloc[q]) >> 3;
        dval[q] = fmaf(wa, g_diag[row0 + rloc[q]], bb);
    }

    // lane-invariant ldmatrix address components
    const uint32_t rA = (uint32_t)(wm * 64 + (l & 15)) * 128 + ((l >> 4) << 4);
    const uint32_t nB = (uint32_t)(((l >> 4) << 3) + (l & 7)) * 128 +
                        (((l >> 3) & 1) << 4) + (uint32_t)wn * 8192;

    float s[8];
#pragma unroll
    for (int q = 0; q < 8; ++q) s[q] = 0.f;

    for (int pass = 0; pass < NPASS; ++pass) {
        float acc[4][8][4];
#pragma unroll
        for (int rb = 0; rb < 4; ++rb)
#pragma unroll
            for (int f = 0; f < 8; ++f)
                acc[rb][f][0] = acc[rb][f][1] = acc[rb][f][2] = acc[rb][f][3] = 0.f;

        for (int kc = 0; kc < NKC; ++kc) {
            const int g = pass * NKC + kc;
            CPWAIT0();                 // chunk g resident (this thread's part)
            __syncthreads();           // everyone's copies visible; old buf free
            issueB(g + 1);             // prefetch next chunk into other buffer

            const uint32_t abase = sb + SM_A + kc * 16384;
            const uint32_t bbase = sb + SM_B + (g & 1) * 32768;
#pragma unroll
            for (int ks = 0; ks < 4; ++ks) {
                uint32_t a[4][4];
#pragma unroll
                for (int rb = 0; rb < 4; ++rb)
                    ldsm_x4(a[rb], abase + sw128(rA + rb * 2048 + ks * 32));
#pragma unroll
                for (int f2 = 0; f2 < 4; ++f2) {
                    uint32_t b[4];
                    ldsm_x4t(b, bbase + sw128(nB + f2 * 2048 + ks * 32));
#pragma unroll
                    for (int rb = 0; rb < 4; ++rb) {
                        mma16816(acc[rb][2 * f2],     a[rb], b[0], b[1]);
                        mma16816(acc[rb][2 * f2 + 1], a[rb], b[2], b[3]);
                    }
                }
            }
        }

        // ---- epilogue: scale + diag replace + exp-sum over this warp's 64 cols
        const int n0 = pass * NT + wn * 64;
#pragma unroll
        for (int rb = 0; rb < 4; ++rb) {
#pragma unroll
            for (int f = 0; f < 8; ++f) {
                const int c = n0 + f * 8 + (l & 3) * 2;
                float x00 = fmaf(wa, acc[rb][f][0], bb);
                float x01 = fmaf(wa, acc[rb][f][1], bb);
                float x10 = fmaf(wa, acc[rb][f][2], bb);
                float x11 = fmaf(wa, acc[rb][f][3], bb);
                if (c     == spk[rb * 2])     x00 = dval[rb * 2];
                if (c + 1 == spk[rb * 2])     x01 = dval[rb * 2];
                if (c     == spk[rb * 2 + 1]) x10 = dval[rb * 2 + 1];
                if (c + 1 == spk[rb * 2 + 1]) x11 = dval[rb * 2 + 1];
                s[rb * 2]     += __expf(x00) + __expf(x01);
                s[rb * 2 + 1] += __expf(x10) + __expf(x11);
            }
        }
    }

    // ---- reduce the 4 lanes (quad) sharing each row
#pragma unroll
    for (int q = 0; q < 8; ++q) {
        s[q] += __shfl_xor_sync(0xffffffffu, s[q], 1);
        s[q] += __shfl_xor_sync(0xffffffffu, s[q], 2);
    }

    // ---- combine the 4 column warps (wn=0..3) per row via smem
    float* red = (float*)(smem + SM_RED);
    __syncthreads();
    if (wn > 0 && (l & 3) == 0) {
#pragma unroll
        for (int q = 0; q < 8; ++q) red[(wn - 1) * 128 + rloc[q]] = s[q];
    }
    __syncthreads();
    float part = 0.f;
    if (wn == 0 && (l & 3) == 0) {
#pragma unroll
        for (int q = 0; q < 8; ++q) {
            float tot = s[q] + red[rloc[q]] + red[128 + rloc[q]] +
                        red[256 + rloc[q]];
            part += __logf(tot) - dval[q];
        }
    }
    part += __shfl_xor_sync(0xffffffffu, part, 4);
    part += __shfl_xor_sync(0xffffffffu, part, 8);
    part += __shfl_xor_sync(0xffffffffu, part, 16);
    if (wn == 0 && l == 0) atomicAdd(out, part * (1.0f / N_ROWS));
}

// ---------------------------------------------------------------------------
extern "C" void kernel_launch(void* const* d_in, const int* in_sizes, int n_in,
                              void* d_out, int out_size) {
    const float* e = (const float*)d_in[0];   // embeds [16384,512] f32
    const float* w = (const float*)d_in[1];   // scalar
    const float* b = (const float*)d_in[2];   // scalar
    float* out = (float*)d_out;

    cudaFuncSetAttribute(loss_kernel, cudaFuncAttributeMaxDynamicSharedMemorySize,
                         SMEM_TOTAL);
    prep_kernel<<<N_SPK, 64>>>(e, out);
    loss_kernel<<<N_ROWS / MT, 256, SMEM_TOTAL>>>(w, b, out);
}